// round 1
// baseline (speedup 1.0000x reference)
#include <cuda_runtime.h>

#define L_SEQ 1024
#define KNN   48
#define H     128
#define HP    64      // H/2 (float2 pairs along h)
#define PST   65      // padded P row stride in float2 units (bank-conflict free)

// scratch (allocation-free: __device__ globals)
__device__ float  d_hv[L_SEQ * H];          // LN+W1 output, 512 KB
__device__ float2 d_W2p[HP * H];            // W2 packed: [hp][o] = (W2[o,2hp], W2[o,2hp+1])

// ---------------------------------------------------------------------------
// packed f32x2 helpers (Blackwell 2x-FP32 path; ptxas won't auto-fuse)
// ---------------------------------------------------------------------------
__device__ __forceinline__ void fma2(unsigned long long& d,
                                     unsigned long long a,
                                     unsigned long long b) {
    asm("fma.rn.f32x2 %0, %1, %2, %0;" : "+l"(d) : "l"(a), "l"(b));
}
__device__ __forceinline__ float2 unpack2(unsigned long long v) {
    float2 r;
    asm("mov.b64 {%0,%1}, %2;" : "=f"(r.x), "=f"(r.y) : "l"(v));
    return r;
}

// ---------------------------------------------------------------------------
// Kernel 0: pack W2 [o,h] row-major -> d_W2p[hp][o] as float2 along h
// ---------------------------------------------------------------------------
__global__ void pack_w2_kernel(const float* __restrict__ W2) {
    int idx = blockIdx.x * blockDim.x + threadIdx.x;   // 0..8191
    if (idx >= HP * H) return;
    int hp = idx >> 7;        // 0..63
    int o  = idx & 127;       // 0..127
    d_W2p[idx] = make_float2(W2[o * H + 2 * hp], W2[o * H + 2 * hp + 1]);
}

// ---------------------------------------------------------------------------
// Kernel 1: LayerNorm + Linear1  ->  d_hv[i][o]
// one block per row i, 128 threads (thread t owns output o = t)
// ---------------------------------------------------------------------------
__global__ void __launch_bounds__(128) ln_w1_kernel(
    const float* __restrict__ hV,
    const float* __restrict__ W1,
    const float* __restrict__ b1,
    const float* __restrict__ ln_scale,
    const float* __restrict__ ln_bias) {
    int i = blockIdx.x;
    int t = threadIdx.x;

    __shared__ float xs[H];
    __shared__ float red[8];

    float x = hV[i * H + t];

    // mean
    float s = x;
    #pragma unroll
    for (int off = 16; off; off >>= 1) s += __shfl_xor_sync(~0u, s, off);
    if ((t & 31) == 0) red[t >> 5] = s;
    __syncthreads();
    float mu = (red[0] + red[1] + red[2] + red[3]) * (1.0f / H);

    // variance
    float d  = x - mu;
    float sq = d * d;
    #pragma unroll
    for (int off = 16; off; off >>= 1) sq += __shfl_xor_sync(~0u, sq, off);
    if ((t & 31) == 0) red[4 + (t >> 5)] = sq;
    __syncthreads();
    float var = (red[4] + red[5] + red[6] + red[7]) * (1.0f / H);

    float ln = d * rsqrtf(var + 1e-5f) * ln_scale[t] + ln_bias[t];
    xs[t] = ln;
    __syncthreads();

    // hv[o=t] = b1[t] + dot(ln, W1[t,:])
    float acc = b1[t];
    const float4* w = reinterpret_cast<const float4*>(W1 + t * H);
    const float4* l = reinterpret_cast<const float4*>(xs);
    #pragma unroll
    for (int q = 0; q < H / 4; q++) {
        float4 a = w[q], b = l[q];
        acc += a.x * b.x + a.y * b.y + a.z * b.z + a.w * b.w;
    }
    d_hv[i * H + t] = acc;
}

// ---------------------------------------------------------------------------
// Kernel 2 (dominant): per row i:
//   P[k,h] = hv[i,h] * hv[E_idx[i,k], h]      (smem, f32x2-paired, padded)
//   out[i,k,o] = dot(P[k,:], W2[o,:]) + b2[o]  (register-tiled 6k x 8o, FFMA2)
// persistent blocks: W2 staged to smem once per block.
// ---------------------------------------------------------------------------
#define SMEM_W_BYTES  (HP * H * 8)          // 65536
#define SMEM_P_BYTES  (KNN * PST * 8)       // 24960
#define SMEM_HI_OFF   (SMEM_W_BYTES + SMEM_P_BYTES)
#define SMEM_IDX_OFF  (SMEM_HI_OFF + 512)
#define SMEM_TOTAL    (SMEM_IDX_OFF + KNN * 4)   // 91152 B

__global__ void __launch_bounds__(128) outer_w2_kernel(
    const int*   __restrict__ Eidx,
    const float* __restrict__ b2,
    float*       __restrict__ out) {
    extern __shared__ char smem[];
    unsigned long long* sW  = reinterpret_cast<unsigned long long*>(smem);
    unsigned long long* sP  = reinterpret_cast<unsigned long long*>(smem + SMEM_W_BYTES);
    float2*             sHi = reinterpret_cast<float2*>(smem + SMEM_HI_OFF);
    int*                sIx = reinterpret_cast<int*>(smem + SMEM_IDX_OFF);

    int t  = threadIdx.x;
    int kt = t >> 4;    // 0..7  : k-tile (6 k's each)
    int ot = t & 15;    // 0..15 : o-tile (8 o's, stride 16)

    // stage W2p once (coalesced LDG.64 -> STS.64)
    {
        const unsigned long long* gW = reinterpret_cast<const unsigned long long*>(d_W2p);
        #pragma unroll
        for (int q = 0; q < HP; q++) sW[q * H + t] = gW[q * H + t];
    }

    // this thread's bias values: o = ot + 16*j
    float myb2[8];
    #pragma unroll
    for (int j = 0; j < 8; j++) myb2[j] = b2[ot + 16 * j];

    const float2* ghv = reinterpret_cast<const float2*>(d_hv);

    for (int i = blockIdx.x; i < L_SEQ; i += gridDim.x) {
        // stage hv_i and edge indices
        if (t < HP)  sHi[t] = ghv[i * HP + t];
        if (t < KNN) sIx[t] = Eidx[i * KNN + t];
        __syncthreads();

        // build P[k][hp] = hv_i[pair hp] * hv_j[pair hp]  (gather j from L2)
        #pragma unroll
        for (int q = 0; q < (KNN * HP) / 128; q++) {   // 24 iters
            int idx = q * 128 + t;
            int k   = idx >> 6;     // 0..47
            int hp  = idx & 63;     // 0..63
            int j   = sIx[k];
            float2 a  = ghv[j * HP + hp];
            float2 hi = sHi[hp];
            float2 p  = make_float2(a.x * hi.x, a.y * hi.y);
            sP[k * PST + hp] = *reinterpret_cast<unsigned long long*>(&p);
        }
        __syncthreads();

        // register-tiled GEMM: C[48,128] = P[48,128] @ W2^T, packed f32x2 along h
        unsigned long long acc[6][8] = {};
        #pragma unroll 4
        for (int hp = 0; hp < HP; hp++) {
            unsigned long long p[6], w[8];
            #pragma unroll
            for (int m = 0; m < 6; m++) p[m] = sP[(kt * 6 + m) * PST + hp];
            #pragma unroll
            for (int j = 0; j < 8; j++) w[j] = sW[hp * H + ot + 16 * j];
            #pragma unroll
            for (int m = 0; m < 6; m++)
                #pragma unroll
                for (int j = 0; j < 8; j++)
                    fma2(acc[m][j], p[m], w[j]);
        }

        // epilogue: horizontal add + bias + store
        #pragma unroll
        for (int m = 0; m < 6; m++) {
            int k = kt * 6 + m;
            float* orow = out + (size_t)(i * KNN + k) * H;
            #pragma unroll
            for (int j = 0; j < 8; j++) {
                float2 v = unpack2(acc[m][j]);
                orow[ot + 16 * j] = v.x + v.y + myb2[j];
            }
        }
        __syncthreads();   // protect sP/sHi/sIx before next iteration's refill
    }
}

// ---------------------------------------------------------------------------
extern "C" void kernel_launch(void* const* d_in, const int* in_sizes, int n_in,
                              void* d_out, int out_size) {
    const float* hV       = (const float*)d_in[0];
    const int*   Eidx     = (const int*)d_in[1];
    const float* W1       = (const float*)d_in[2];
    const float* b1       = (const float*)d_in[3];
    const float* W2       = (const float*)d_in[4];
    const float* b2       = (const float*)d_in[5];
    const float* ln_scale = (const float*)d_in[6];
    const float* ln_bias  = (const float*)d_in[7];
    float* out = (float*)d_out;

    cudaFuncSetAttribute(outer_w2_kernel,
                         cudaFuncAttributeMaxDynamicSharedMemorySize, SMEM_TOTAL);

    pack_w2_kernel<<<(HP * H + 127) / 128, 128>>>(W2);
    ln_w1_kernel<<<L_SEQ, 128>>>(hV, W1, b1, ln_scale, ln_bias);
    // persistent: ~2 CTAs/SM on 148-SM sm_100a
    outer_w2_kernel<<<296, 128, SMEM_TOTAL>>>(Eidx, b2, out);
}

// round 4
// speedup vs baseline: 1.9969x; 1.9969x over previous
#include <cuda_runtime.h>
#include <cstdint>

#define L_SEQ   1024
#define KNN     48
#define H       128
#define N_EDGES (L_SEQ * KNN)     // 49152
#define N_TILES (N_EDGES / 128)   // 384
#define GRID_MAIN 148

__device__ float d_hv[L_SEQ * H];   // LN+W1 output (512 KB scratch)

// smem byte offsets (main kernel)
#define SM_W2HI 0
#define SM_W2LO 32768
#define SM_PHI  65536
#define SM_PLO  98304
#define SM_B2   131072
#define SM_TOTAL (131072 + 512 + 128)   // 131712 B

// ---------------------------------------------------------------------------
// helpers
// ---------------------------------------------------------------------------
__device__ __forceinline__ uint32_t smem_to_u32(const void* p) {
    uint32_t a;
    asm("{ .reg .u64 t; cvta.to.shared.u64 t, %1; cvt.u32.u64 %0, t; }"
        : "=r"(a) : "l"(p));
    return a;
}

// XOR swizzle on 16B chunks within a 256B row (conflict-free ldmatrix/STS)
__device__ __forceinline__ uint32_t swz(uint32_t row, uint32_t chunk) {
    return (chunk & 8u) | ((chunk ^ row) & 7u);
}

// split (a,b) fp32 pair into packed bf16x2 hi + bf16x2 lo (a -> low 16 bits)
__device__ __forceinline__ void split2(float a, float b, uint32_t& hi, uint32_t& lo) {
    uint32_t h;
    asm("cvt.rn.bf16x2.f32 %0, %1, %2;" : "=r"(h) : "f"(b), "f"(a));
    float ha = __uint_as_float(h << 16);
    float hb = __uint_as_float(h & 0xFFFF0000u);
    float la = a - ha;
    float lb = b - hb;
    asm("cvt.rn.bf16x2.f32 %0, %1, %2;" : "=r"(lo) : "f"(lb), "f"(la));
    hi = h;
}

__device__ __forceinline__ void ldsm_x4(uint32_t* r, uint32_t addr) {
    asm volatile("ldmatrix.sync.aligned.m8n8.x4.shared.b16 {%0,%1,%2,%3}, [%4];"
                 : "=r"(r[0]), "=r"(r[1]), "=r"(r[2]), "=r"(r[3]) : "r"(addr));
}

__device__ __forceinline__ void mma_bf16(float* c, const uint32_t* a,
                                         uint32_t b0, uint32_t b1) {
    asm volatile("mma.sync.aligned.m16n8k16.row.col.f32.bf16.bf16.f32 "
                 "{%0,%1,%2,%3}, {%4,%5,%6,%7}, {%8,%9}, {%0,%1,%2,%3};"
                 : "+f"(c[0]), "+f"(c[1]), "+f"(c[2]), "+f"(c[3])
                 : "r"(a[0]), "r"(a[1]), "r"(a[2]), "r"(a[3]), "r"(b0), "r"(b1));
}

// ---------------------------------------------------------------------------
// Kernel 1: LayerNorm + Linear1 -> d_hv.  16 rows/block, 128 threads.
// ---------------------------------------------------------------------------
__global__ void __launch_bounds__(128) ln_w1_kernel(
    const float* __restrict__ hV, const float* __restrict__ W1,
    const float* __restrict__ b1, const float* __restrict__ ln_scale,
    const float* __restrict__ ln_bias) {
    __shared__ float xs[16][H];
    int t = threadIdx.x, w = t >> 5, lane = t & 31;
    int i0 = blockIdx.x * 16;

    float4 g = reinterpret_cast<const float4*>(ln_scale)[lane];
    float4 c = reinterpret_cast<const float4*>(ln_bias)[lane];

    #pragma unroll
    for (int rr = 0; rr < 4; rr++) {
        int r = w + rr * 4;
        float4 x = reinterpret_cast<const float4*>(hV + (size_t)(i0 + r) * H)[lane];
        float s = x.x + x.y + x.z + x.w;
        #pragma unroll
        for (int off = 16; off; off >>= 1) s += __shfl_xor_sync(~0u, s, off);
        float mu = s * (1.0f / H);
        float4 d = make_float4(x.x - mu, x.y - mu, x.z - mu, x.w - mu);
        float sq = d.x * d.x + d.y * d.y + d.z * d.z + d.w * d.w;
        #pragma unroll
        for (int off = 16; off; off >>= 1) sq += __shfl_xor_sync(~0u, sq, off);
        float rs = rsqrtf(sq * (1.0f / H) + 1e-5f);
        float4 o = make_float4(d.x * rs * g.x + c.x, d.y * rs * g.y + c.y,
                               d.z * rs * g.z + c.z, d.w * rs * g.w + c.w);
        reinterpret_cast<float4*>(xs[r])[lane] = o;
    }
    __syncthreads();

    float acc[16];
    float bt = b1[t];
    #pragma unroll
    for (int r = 0; r < 16; r++) acc[r] = bt;
    const float4* wrow = reinterpret_cast<const float4*>(W1 + (size_t)t * H);
    #pragma unroll 4
    for (int q = 0; q < H / 4; q++) {
        float4 w4 = wrow[q];
        #pragma unroll
        for (int r = 0; r < 16; r++) {
            float4 x4 = reinterpret_cast<const float4*>(xs[r])[q];
            acc[r] += w4.x * x4.x + w4.y * x4.y + w4.z * x4.z + w4.w * x4.w;
        }
    }
    #pragma unroll
    for (int r = 0; r < 16; r++) d_hv[(size_t)(i0 + r) * H + t] = acc[r];
}

// ---------------------------------------------------------------------------
// Kernel 2: C[49152,128] = P @ W2^T via mma.sync bf16, 3-term split.
// 256 threads = 8 warps; tile = 128 edges; warp w owns rows [16w,16w+16).
// ---------------------------------------------------------------------------
__global__ void __launch_bounds__(256, 1) outer_w2_mma_kernel(
    const int* __restrict__ Eidx, const float* __restrict__ W2,
    const float* __restrict__ b2, float* __restrict__ out) {
    extern __shared__ char smemc[];
    const uint32_t sb = smem_to_u32(smemc);
    int t = threadIdx.x;
    int warp = t >> 5, lane = t & 31;

    // ---- stage W2 hi/lo (bf16, swizzled [o][h]) + b2 ----
    #pragma unroll
    for (int it = 0; it < 8; it++) {
        int g = it * 256 + t;          // 0..2047 chunk index
        int o = g >> 4;                // row (output feature)
        int ch = g & 15;               // 16B chunk within row
        const float4* w = reinterpret_cast<const float4*>(W2 + (size_t)o * H + ch * 8);
        float4 w0 = w[0], w1 = w[1];
        uint4 hi4, lo4;
        split2(w0.x, w0.y, hi4.x, lo4.x);
        split2(w0.z, w0.w, hi4.y, lo4.y);
        split2(w1.x, w1.y, hi4.z, lo4.z);
        split2(w1.z, w1.w, hi4.w, lo4.w);
        uint32_t off = (uint32_t)o * 256 + swz(o, ch) * 16;
        *reinterpret_cast<uint4*>(smemc + SM_W2HI + off) = hi4;
        *reinterpret_cast<uint4*>(smemc + SM_W2LO + off) = lo4;
    }
    if (t < 128) reinterpret_cast<float*>(smemc + SM_B2)[t] = b2[t];
    __syncthreads();

    // precomputed ldmatrix lane-address components
    const uint32_t m_in_tile = (uint32_t)(warp * 16 + (lane & 15));     // A row
    const uint32_t a_rowoff  = m_in_tile * 256;
    const uint32_t a_sel     = (uint32_t)(lane >> 4);                   // k halves
    const uint32_t b_row7    = (uint32_t)(lane & 7);                    // B row (n)
    const uint32_t b_rowoff  = b_row7 * 256;
    const uint32_t b_sel     = (uint32_t)(lane >> 3);                   // 0..3

    for (int tile = blockIdx.x; tile < N_TILES; tile += gridDim.x) {
        // ---- build P hi/lo in smem (gather) ----
        {
            int m = t >> 1;                  // edge row in tile
            int half = t & 1;                // h half (64 each)
            int e = tile * 128 + m;
            int i = (int)((unsigned)e / KNN);
            int j = __ldg(Eidx + e);
            const float4* pi = reinterpret_cast<const float4*>(
                d_hv + (size_t)i * H + half * 64);
            const float4* pj = reinterpret_cast<const float4*>(
                d_hv + (size_t)j * H + half * 64);
            uint32_t rowbase = (uint32_t)m * 256;
            #pragma unroll
            for (int q = 0; q < 8; q++) {
                float4 x0 = pi[2 * q], x1 = pi[2 * q + 1];
                float4 y0 = pj[2 * q], y1 = pj[2 * q + 1];
                uint4 hi4, lo4;
                split2(x0.x * y0.x, x0.y * y0.y, hi4.x, lo4.x);
                split2(x0.z * y0.z, x0.w * y0.w, hi4.y, lo4.y);
                split2(x1.x * y1.x, x1.y * y1.y, hi4.z, lo4.z);
                split2(x1.z * y1.z, x1.w * y1.w, hi4.w, lo4.w);
                uint32_t off = rowbase + swz((uint32_t)m, (uint32_t)(half * 8 + q)) * 16;
                *reinterpret_cast<uint4*>(smemc + SM_PHI + off) = hi4;
                *reinterpret_cast<uint4*>(smemc + SM_PLO + off) = lo4;
            }
        }
        __syncthreads();

        // ---- warp GEMM: 16 rows x 128 cols, K=128, 3-term bf16 ----
        float acc[16][4];
        #pragma unroll
        for (int nt = 0; nt < 16; nt++)
            #pragma unroll
            for (int q = 0; q < 4; q++) acc[nt][q] = 0.0f;

        #pragma unroll
        for (int kp = 0; kp < 4; kp++) {        // k-step pairs (k32 each)
            uint32_t ah[2][4], al[2][4];
            #pragma unroll
            for (int ss = 0; ss < 2; ss++) {
                uint32_t chunkA = (uint32_t)((2 * kp + ss) * 2) + a_sel;
                uint32_t aaddr = sb + SM_PHI + a_rowoff + swz(m_in_tile, chunkA) * 16;
                ldsm_x4(ah[ss], aaddr);
                ldsm_x4(al[ss], aaddr + (SM_PLO - SM_PHI));
            }
            uint32_t chunkB = (uint32_t)(kp * 4) + b_sel;
            uint32_t bcol = swz(b_row7, chunkB) * 16;
            #pragma unroll
            for (int nt = 0; nt < 16; nt++) {
                uint32_t baddr = sb + SM_W2HI + (uint32_t)nt * 2048 + b_rowoff + bcol;
                uint32_t bh[4], bl[4];
                ldsm_x4(bh, baddr);
                ldsm_x4(bl, baddr + (SM_W2LO - SM_W2HI));
                mma_bf16(acc[nt], ah[0], bh[0], bh[1]);   // hi*hi (k lo half)
                mma_bf16(acc[nt], ah[0], bl[0], bl[1]);   // hi*lo
                mma_bf16(acc[nt], al[0], bh[0], bh[1]);   // lo*hi
                mma_bf16(acc[nt], ah[1], bh[2], bh[3]);   // hi*hi (k hi half)
                mma_bf16(acc[nt], ah[1], bl[2], bl[3]);
                mma_bf16(acc[nt], al[1], bh[2], bh[3]);
            }
        }

        // ---- epilogue: + b2, store ----
        {
            int r0 = tile * 128 + warp * 16 + (lane >> 2);
            int cbase = (lane & 3) * 2;
            float* orow0 = out + (size_t)r0 * H;
            float* orow1 = orow0 + 8 * H;
            #pragma unroll
            for (int nt = 0; nt < 16; nt++) {
                float2 bb = *reinterpret_cast<const float2*>(
                    smemc + SM_B2 + nt * 32 + (lane & 3) * 8);
                float2 v0 = make_float2(acc[nt][0] + bb.x, acc[nt][1] + bb.y);
                float2 v1 = make_float2(acc[nt][2] + bb.x, acc[nt][3] + bb.y);
                *reinterpret_cast<float2*>(orow0 + nt * 8 + cbase) = v0;
                *reinterpret_cast<float2*>(orow1 + nt * 8 + cbase) = v1;
            }
        }
        __syncthreads();   // all warps done reading sP before next build
    }
}

// ---------------------------------------------------------------------------
extern "C" void kernel_launch(void* const* d_in, const int* in_sizes, int n_in,
                              void* d_out, int out_size) {
    const float* hV       = (const float*)d_in[0];
    const int*   Eidx     = (const int*)d_in[1];
    const float* W1       = (const float*)d_in[2];
    const float* b1       = (const float*)d_in[3];
    const float* W2       = (const float*)d_in[4];
    const float* b2       = (const float*)d_in[5];
    const float* ln_scale = (const float*)d_in[6];
    const float* ln_bias  = (const float*)d_in[7];
    float* out = (float*)d_out;

    cudaFuncSetAttribute(outer_w2_mma_kernel,
                         cudaFuncAttributeMaxDynamicSharedMemorySize, SM_TOTAL);

    ln_w1_kernel<<<L_SEQ / 16, 128>>>(hV, W1, b1, ln_scale, ln_bias);
    outer_w2_mma_kernel<<<GRID_MAIN, 256, SM_TOTAL>>>(Eidx, W2, b2, out);
}